// round 5
// baseline (speedup 1.0000x reference)
#include <cuda_runtime.h>

#define N_NODES 10000
#define E_TOTAL 640000
#define D_NODE 128
#define D_EDGE 64
#define D_IN 192
#define D_OUT 128

#define BE 64          // edges per block
#define KC 32          // K chunk
#define NTHREADS 256
#define AS_STRIDE 68   // 64 + 4 pad: float4-aligned, reduces STS conflicts

__device__ float g_cnt[N_NODES];
__device__ int   g_idx64;   // 1 if edge_index is int64, 0 if int32

// -------------------------------------------------------------------------
// Zero output + counts, and sniff edge_index dtype.
// int64 nonneg small values => every odd 32-bit word is 0.
// -------------------------------------------------------------------------
__global__ void zero_kernel(float* __restrict__ out, const unsigned* __restrict__ eiw) {
    int i = blockIdx.x * blockDim.x + threadIdx.x;
    if (i < N_NODES * D_OUT) out[i] = 0.0f;
    if (i < N_NODES) g_cnt[i] = 0.0f;
    if (blockIdx.x == 0 && threadIdx.x == 0) {
        int is64 = 1;
        #pragma unroll 1
        for (int k = 0; k < 64; k++) {
            unsigned hi = eiw[2 * k + 1];
            if (hi != 0u && hi != 0xFFFFFFFFu) { is64 = 0; break; }
        }
        g_idx64 = is64;
    }
}

__device__ __forceinline__ int clampi(int v, int lo, int hi) {
    return v < lo ? lo : (v > hi ? hi : v);
}

// -------------------------------------------------------------------------
// Fused gather + GEMM + scatter-add (+ per-edge count)
// Tile: 64 edges x 128 out-cols, K chunked by 32.
//   chunks 0..3 : x[src][ch*32 .. +31] ; chunks 4..5 : ef[e][(ch-4)*32 .. +31]
// Thread (tcol = tid&31, trow = tid>>5) computes 8 edges x 4 cols.
// -------------------------------------------------------------------------
__global__ void __launch_bounds__(NTHREADS)
gemm_scatter_kernel(const float* __restrict__ x,
                    const void* __restrict__ ei_raw,
                    const float* __restrict__ ef,
                    const float* __restrict__ W,
                    float* __restrict__ out)
{
    __shared__ float As[KC][AS_STRIDE];
    __shared__ float Ws[KC][D_OUT];
    __shared__ int s_src[BE];
    __shared__ int s_dst[BE];

    const int tid = threadIdx.x;
    const int e0  = blockIdx.x * BE;
    const int is64 = g_idx64;

    if (tid < BE) {
        int s, d;
        if (is64) {
            const long long* ei = (const long long*)ei_raw;
            s = (int)ei[e0 + tid];
            d = (int)ei[E_TOTAL + e0 + tid];
        } else {
            const int* ei = (const int*)ei_raw;
            s = ei[e0 + tid];
            d = ei[E_TOTAL + e0 + tid];
        }
        s = clampi(s, 0, N_NODES - 1);
        d = clampi(d, 0, N_NODES - 1);
        s_src[tid] = s;
        s_dst[tid] = d;
        atomicAdd(&g_cnt[d], 1.0f);       // fused degree count
    }
    __syncthreads();

    const int tcol = tid & 31;            // cols tcol*4 .. +3
    const int trow = tid >> 5;            // rows trow*8 .. +7

    float acc[8][4];
#pragma unroll
    for (int r = 0; r < 8; r++)
#pragma unroll
        for (int c = 0; c < 4; c++) acc[r][c] = 0.0f;

    const int ge = tid >> 2;              // edge 0..63
    const int gq = tid & 3;               // quarter 0..3

#pragma unroll 1
    for (int ch = 0; ch < 6; ch++) {
        // ---- stage global loads into registers ----
        const float* abase;
        if (ch < 4) abase = x + (size_t)s_src[ge] * D_NODE + ch * KC;
        else        abase = ef + (size_t)(e0 + ge) * D_EDGE + (ch - 4) * KC;
        float4 v0 = ((const float4*)abase)[gq];
        float4 v1 = ((const float4*)abase)[gq + 4];

        const float4* wsrc = (const float4*)(W + ch * KC * D_OUT);
        float4 w0 = wsrc[tid];
        float4 w1 = wsrc[tid + 256];
        float4 w2 = wsrc[tid + 512];
        float4 w3 = wsrc[tid + 768];

        __syncthreads();                  // previous chunk's compute done

        // ---- store A transposed: As[k][e] ----
        {
            int k0 = gq * 4;
            As[k0 + 0][ge] = v0.x;
            As[k0 + 1][ge] = v0.y;
            As[k0 + 2][ge] = v0.z;
            As[k0 + 3][ge] = v0.w;
            int k1 = (gq + 4) * 4;
            As[k1 + 0][ge] = v1.x;
            As[k1 + 1][ge] = v1.y;
            As[k1 + 2][ge] = v1.z;
            As[k1 + 3][ge] = v1.w;
        }
        {
            float4* wdst = (float4*)&Ws[0][0];
            wdst[tid]       = w0;
            wdst[tid + 256] = w1;
            wdst[tid + 512] = w2;
            wdst[tid + 768] = w3;
        }
        __syncthreads();

        // ---- compute ----
#pragma unroll
        for (int k = 0; k < KC; k++) {
            float4 a0 = *(const float4*)&As[k][trow * 8];
            float4 a1 = *(const float4*)&As[k][trow * 8 + 4];
            float4 b  = *(const float4*)&Ws[k][tcol * 4];

            acc[0][0] += a0.x * b.x; acc[0][1] += a0.x * b.y; acc[0][2] += a0.x * b.z; acc[0][3] += a0.x * b.w;
            acc[1][0] += a0.y * b.x; acc[1][1] += a0.y * b.y; acc[1][2] += a0.y * b.z; acc[1][3] += a0.y * b.w;
            acc[2][0] += a0.z * b.x; acc[2][1] += a0.z * b.y; acc[2][2] += a0.z * b.z; acc[2][3] += a0.z * b.w;
            acc[3][0] += a0.w * b.x; acc[3][1] += a0.w * b.y; acc[3][2] += a0.w * b.z; acc[3][3] += a0.w * b.w;
            acc[4][0] += a1.x * b.x; acc[4][1] += a1.x * b.y; acc[4][2] += a1.x * b.z; acc[4][3] += a1.x * b.w;
            acc[5][0] += a1.y * b.x; acc[5][1] += a1.y * b.y; acc[5][2] += a1.y * b.z; acc[5][3] += a1.y * b.w;
            acc[6][0] += a1.z * b.x; acc[6][1] += a1.z * b.y; acc[6][2] += a1.z * b.z; acc[6][3] += a1.z * b.w;
            acc[7][0] += a1.w * b.x; acc[7][1] += a1.w * b.y; acc[7][2] += a1.w * b.z; acc[7][3] += a1.w * b.w;
        }
    }

    // ---- scatter-add epilogue (scalar REDG) ----
#pragma unroll
    for (int r = 0; r < 8; r++) {
        int e = trow * 8 + r;
        float* p = out + (size_t)s_dst[e] * D_OUT + tcol * 4;
        atomicAdd(p + 0, acc[r][0]);
        atomicAdd(p + 1, acc[r][1]);
        atomicAdd(p + 2, acc[r][2]);
        atomicAdd(p + 3, acc[r][3]);
    }
}

// -------------------------------------------------------------------------
// Divide by count, add bias (b per-edge in reference: mean(h)+b when cnt>0)
// -------------------------------------------------------------------------
__global__ void finalize_kernel(float* __restrict__ out, const float* __restrict__ b) {
    int i = blockIdx.x * blockDim.x + threadIdx.x;
    if (i >= N_NODES * D_OUT) return;
    int node = i >> 7;
    float c = g_cnt[node];
    float v = out[i];
    out[i] = (c > 0.0f) ? (v / c + b[i & (D_OUT - 1)]) : 0.0f;
}

// -------------------------------------------------------------------------
// Launch
// -------------------------------------------------------------------------
extern "C" void kernel_launch(void* const* d_in, const int* in_sizes, int n_in,
                              void* d_out, int out_size)
{
    const float* x  = (const float*)d_in[0];
    const void*  ei = d_in[1];
    const float* ef = (const float*)d_in[2];
    const float* W  = (const float*)d_in[3];
    const float* b  = (const float*)d_in[4];
    float* out = (float*)d_out;

    const int total = N_NODES * D_OUT;
    zero_kernel<<<(total + 255) / 256, 256>>>(out, (const unsigned*)ei);
    gemm_scatter_kernel<<<E_TOTAL / BE, NTHREADS>>>(x, ei, ef, W, out);
    finalize_kernel<<<(total + 255) / 256, 256>>>(out, b);
}

// round 12
// speedup vs baseline: 1.8720x; 1.8720x over previous
#include <cuda_runtime.h>
#include <cstdint>

#define N_NODES 10000
#define E_TOTAL 640000
#define D_NODE 128
#define D_EDGE 64
#define D_IN 192
#define D_OUT 128

#define TM 256              // edges per CTA
#define NTHREADS 512        // 16 warps
#define KCH 96              // K chunk
#define A_STRIDE 100        // 100 mod 32 = 4  -> conflict-free A frags
#define W_STRIDE 136        // 136 mod 32 = 8  -> conflict-free B frags

#define SMEM_A_WORDS (TM * A_STRIDE)            // 25600
#define SMEM_W_WORDS (KCH * W_STRIDE)           // 13056
#define SMEM_BYTES ((SMEM_A_WORDS + SMEM_W_WORDS) * 4)   // 154624

__device__ float g_cnt[N_NODES];
__device__ int   g_idx64;

__device__ __forceinline__ uint32_t f2tf32(float f) {
    uint32_t u;
    asm("cvt.rna.tf32.f32 %0, %1;" : "=r"(u) : "f"(f));
    return u;
}
__device__ __forceinline__ void mma_tf32(float* d, const uint32_t* a,
                                         uint32_t b0, uint32_t b1) {
    asm volatile(
        "mma.sync.aligned.m16n8k8.row.col.f32.tf32.tf32.f32 "
        "{%0,%1,%2,%3}, {%4,%5,%6,%7}, {%8,%9}, {%0,%1,%2,%3};"
        : "+f"(d[0]), "+f"(d[1]), "+f"(d[2]), "+f"(d[3])
        : "r"(a[0]), "r"(a[1]), "r"(a[2]), "r"(a[3]), "r"(b0), "r"(b1));
}
__device__ __forceinline__ int clampi(int v, int lo, int hi) {
    return v < lo ? lo : (v > hi ? hi : v);
}

// -------------------------------------------------------------------------
__global__ void zero_kernel(float* __restrict__ out, const unsigned* __restrict__ eiw) {
    int i = blockIdx.x * blockDim.x + threadIdx.x;
    if (i < N_NODES * D_OUT) out[i] = 0.0f;
    if (i < N_NODES) g_cnt[i] = 0.0f;
    if (blockIdx.x == 0 && threadIdx.x == 0) {
        int is64 = 1;
        #pragma unroll 1
        for (int k = 0; k < 64; k++) {
            unsigned hi = eiw[2 * k + 1];
            if (hi != 0u && hi != 0xFFFFFFFFu) { is64 = 0; break; }
        }
        g_idx64 = is64;
    }
}

// -------------------------------------------------------------------------
// Fused gather + tf32 mma.sync GEMM + scatter-add.
// CTA: 256 edges x 128 cols, K = 2 chunks of 96.
// Warp w: rows (w>>1)*32 .. +31, cols (w&1)*64 .. +63.
// -------------------------------------------------------------------------
extern __shared__ uint32_t dsm[];

__global__ void __launch_bounds__(NTHREADS, 1)
gemm_scatter_mma(const float* __restrict__ x,
                 const void* __restrict__ ei_raw,
                 const float* __restrict__ ef,
                 const float* __restrict__ W,
                 float* __restrict__ out)
{
    __shared__ int s_src[TM];
    __shared__ int s_dst[TM];

    uint32_t* sA = dsm;                      // [TM][A_STRIDE]
    uint32_t* sW = dsm + SMEM_A_WORDS;       // [KCH][W_STRIDE]

    const int tid = threadIdx.x;
    const int wid = tid >> 5;
    const int lane = tid & 31;
    const int e0 = blockIdx.x * TM;

    if (tid < TM) {
        int s, d;
        if (g_idx64) {
            const long long* ei = (const long long*)ei_raw;
            s = (int)ei[e0 + tid];
            d = (int)ei[E_TOTAL + e0 + tid];
        } else {
            const int* ei = (const int*)ei_raw;
            s = ei[e0 + tid];
            d = ei[E_TOTAL + e0 + tid];
        }
        s_src[tid] = clampi(s, 0, N_NODES - 1);
        s_dst[tid] = clampi(d, 0, N_NODES - 1);
        atomicAdd(&g_cnt[s_dst[tid]], 1.0f);
    }

    const int rowband = (wid >> 1) * 32;
    const int colh = (wid & 1) * 64;
    const int lq = lane >> 2;      // 0..7
    const int lr = lane & 3;       // 0..3

    float acc[2][8][4];
#pragma unroll
    for (int m = 0; m < 2; m++)
#pragma unroll
        for (int nt = 0; nt < 8; nt++)
#pragma unroll
            for (int c = 0; c < 4; c++) acc[m][nt][c] = 0.0f;

#pragma unroll 1
    for (int ch = 0; ch < 2; ch++) {
        __syncthreads();   // smem free (also orders s_src on first pass)

        // ---- stage A chunk: 256 rows x 96 cols (24 float4 per row) ----
        #pragma unroll 2
        for (int idx = tid; idx < TM * 24; idx += NTHREADS) {
            int e = idx / 24, q = idx - e * 24;
            float4 v;
            if (ch == 0) {
                v = ((const float4*)(x + (size_t)s_src[e] * D_NODE))[q];
            } else {
                if (q < 8) v = ((const float4*)(x + (size_t)s_src[e] * D_NODE))[24 + q];
                else       v = ((const float4*)(ef + (size_t)(e0 + e) * D_EDGE))[q - 8];
            }
            uint4 t;
            t.x = f2tf32(v.x); t.y = f2tf32(v.y);
            t.z = f2tf32(v.z); t.w = f2tf32(v.w);
            *(uint4*)(sA + e * A_STRIDE + q * 4) = t;
        }
        // ---- stage W chunk: 96 rows x 128 cols ----
        #pragma unroll 2
        for (int idx = tid; idx < KCH * 32; idx += NTHREADS) {
            int k = idx >> 5, nq = idx & 31;
            float4 v = ((const float4*)(W + (size_t)(ch * KCH + k) * D_OUT))[nq];
            uint4 t;
            t.x = f2tf32(v.x); t.y = f2tf32(v.y);
            t.z = f2tf32(v.z); t.w = f2tf32(v.w);
            *(uint4*)(sW + k * W_STRIDE + nq * 4) = t;
        }
        __syncthreads();

        // ---- 12 k-steps of m16n8k8 ----
#pragma unroll
        for (int s = 0; s < KCH / 8; s++) {
            const int kb = s * 8;
            uint32_t a[2][4];
            {
                const uint32_t* pa = sA + (rowband + lq) * A_STRIDE + kb + lr;
                a[0][0] = pa[0];
                a[0][1] = pa[8 * A_STRIDE];
                a[0][2] = pa[4];
                a[0][3] = pa[8 * A_STRIDE + 4];
                a[1][0] = pa[16 * A_STRIDE];
                a[1][1] = pa[24 * A_STRIDE];
                a[1][2] = pa[16 * A_STRIDE + 4];
                a[1][3] = pa[24 * A_STRIDE + 4];
            }
            const uint32_t* pb0 = sW + (kb + lr) * W_STRIDE + colh + lq;
            const uint32_t* pb1 = pb0 + 4 * W_STRIDE;
#pragma unroll
            for (int nt = 0; nt < 8; nt++) {
                uint32_t b0 = pb0[nt * 8];
                uint32_t b1 = pb1[nt * 8];
                mma_tf32(acc[0][nt], a[0], b0, b1);
                mma_tf32(acc[1][nt], a[1], b0, b1);
            }
        }
    }

    // ---- scatter-add epilogue ----
#pragma unroll
    for (int m = 0; m < 2; m++) {
        int r = rowband + m * 16 + lq;
        float* p0 = out + (size_t)s_dst[r] * D_OUT;
        float* p1 = out + (size_t)s_dst[r + 8] * D_OUT;
        int cb = colh + 2 * lr;
#pragma unroll
        for (int nt = 0; nt < 8; nt++) {
            atomicAdd(p0 + cb + nt * 8,     acc[m][nt][0]);
            atomicAdd(p0 + cb + nt * 8 + 1, acc[m][nt][1]);
            atomicAdd(p1 + cb + nt * 8,     acc[m][nt][2]);
            atomicAdd(p1 + cb + nt * 8 + 1, acc[m][nt][3]);
        }
    }
}

// -------------------------------------------------------------------------
__global__ void finalize_kernel(float* __restrict__ out, const float* __restrict__ b) {
    int i = blockIdx.x * blockDim.x + threadIdx.x;
    if (i >= N_NODES * D_OUT) return;
    int node = i >> 7;
    float c = g_cnt[node];
    float v = out[i];
    out[i] = (c > 0.0f) ? (v / c + b[i & (D_OUT - 1)]) : 0.0f;
}

// -------------------------------------------------------------------------
extern "C" void kernel_launch(void* const* d_in, const int* in_sizes, int n_in,
                              void* d_out, int out_size)
{
    const float* x  = (const float*)d_in[0];
    const void*  ei = d_in[1];
    const float* ef = (const float*)d_in[2];
    const float* W  = (const float*)d_in[3];
    const float* b  = (const float*)d_in[4];
    float* out = (float*)d_out;

    cudaFuncSetAttribute(gemm_scatter_mma,
                         cudaFuncAttributeMaxDynamicSharedMemorySize, SMEM_BYTES);

    const int total = N_NODES * D_OUT;
    zero_kernel<<<(total + 255) / 256, 256>>>(out, (const unsigned*)ei);
    gemm_scatter_mma<<<E_TOTAL / TM, NTHREADS, SMEM_BYTES>>>(x, ei, ef, W, out);
    finalize_kernel<<<(total + 255) / 256, 256>>>(out, b);
}